// round 13
// baseline (speedup 1.0000x reference)
#include <cuda_runtime.h>
#include <cstdint>

#define M_     32
#define N_     2048
#define D_     128
#define L_     32768
#define H_     16
#define QKV3_  6144
#define CHUNK_ 1024
#define NC_    32
#define SK_    64          // keys per subtile
#define NSUB_  16          // CHUNK_/SK_

typedef unsigned long long u64;
typedef unsigned int u32;

__device__ float g_scale[M_];
__device__ float g_qkv[M_ * QKV3_];
__device__ float g_num[H_ * NC_ * M_ * D_];   // [hc][q][d]
__device__ float g_den[H_ * NC_ * M_];

// ---- helpers ----
// tf32 "hi" mask (13-bit mantissa)
__device__ __forceinline__ float mh(float x) {
    return __uint_as_float(__float_as_uint(x) & 0xFFFFE000u);
}
// bf16 "hi" mask (truncation)
__device__ __forceinline__ float bh(float x) {
    return __uint_as_float(__float_as_uint(x) & 0xFFFF0000u);
}
// pack two floats' bf16 truncations
__device__ __forceinline__ u32 bpack(float a, float b) {
    u32 r;
    asm("prmt.b32 %0, %1, %2, 0x7632;" : "=r"(r)
        : "r"(__float_as_uint(a)), "r"(__float_as_uint(b)));
    return r;
}
__device__ __forceinline__ u32 cvta_smem(const void* p) {
    u32 a; asm("{ .reg .u64 t; cvta.to.shared.u64 t, %1; cvt.u32.u64 %0, t; }" : "=r"(a) : "l"(p)); return a;
}
__device__ __forceinline__ void cpasync16(u32 s, const void* g) {
    asm volatile("cp.async.cg.shared.global [%0], [%1], 16;" :: "r"(s), "l"(g));
}
#define CP_COMMIT() asm volatile("cp.async.commit_group;" ::: "memory")
#define CP_WAIT0()  asm volatile("cp.async.wait_group 0;" ::: "memory")
#define CP_WAIT1()  asm volatile("cp.async.wait_group 1;" ::: "memory")

__device__ __forceinline__ void ldsm4(u32& r0, u32& r1, u32& r2, u32& r3, u32 a) {
    asm volatile("ldmatrix.sync.aligned.m8n8.x4.shared.b16 {%0,%1,%2,%3}, [%4];"
        : "=r"(r0), "=r"(r1), "=r"(r2), "=r"(r3) : "r"(a));
}
__device__ __forceinline__ void ldsm2(u32& r0, u32& r1, u32 a) {
    asm volatile("ldmatrix.sync.aligned.m8n8.x2.shared.b16 {%0,%1}, [%2];"
        : "=r"(r0), "=r"(r1) : "r"(a));
}
// bf16 m16n8k16
__device__ __forceinline__ void mma16(float* c, u32 a0, u32 a1, u32 a2, u32 a3,
                                      u32 b0, u32 b1) {
    asm volatile("mma.sync.aligned.m16n8k16.row.col.f32.bf16.bf16.f32 "
        "{%0,%1,%2,%3}, {%4,%5,%6,%7}, {%8,%9}, {%0,%1,%2,%3};"
        : "+f"(c[0]), "+f"(c[1]), "+f"(c[2]), "+f"(c[3])
        : "r"(a0), "r"(a1), "r"(a2), "r"(a3), "r"(b0), "r"(b1));
}
// tf32 m16n8k8
__device__ __forceinline__ void mma8(float* c, float a0, float a1, float a2, float a3,
                                     float b0, float b1) {
    asm volatile("mma.sync.aligned.m16n8k8.row.col.f32.tf32.tf32.f32 "
        "{%0,%1,%2,%3}, {%4,%5,%6,%7}, {%8,%9}, {%0,%1,%2,%3};"
        : "+f"(c[0]), "+f"(c[1]), "+f"(c[2]), "+f"(c[3])
        : "r"(__float_as_uint(a0)), "r"(__float_as_uint(a1)),
          "r"(__float_as_uint(a2)), "r"(__float_as_uint(a3)),
          "r"(__float_as_uint(b0)), "r"(__float_as_uint(b1)));
}

// ---- kernel 1: RMS scales ----
__global__ void rms_kernel(const float* __restrict__ X) {
    int m = blockIdx.x;
    float s = 0.f;
    for (int k = threadIdx.x; k < N_; k += 256) { float v = X[m * N_ + k]; s += v * v; }
    __shared__ float red[256];
    red[threadIdx.x] = s; __syncthreads();
    for (int o = 128; o > 0; o >>= 1) {
        if (threadIdx.x < o) red[threadIdx.x] += red[threadIdx.x + o];
        __syncthreads();
    }
    if (threadIdx.x == 0) g_scale[m] = rsqrtf(red[0] * (1.0f / N_));
}

// ---- kernel 2: QKV GEMM via tf32 mma 3-pass (no atomics) ----
// 96 CTAs: 32m x 64n tile, k=2048 double-buffered in 32-chunks.
// Xs [32 m][36] (pad -> fragment loads conflict-free), Ws [32 k][72].
#define QKC 32
#define QXS 36
#define QWS 72
__global__ __launch_bounds__(256) void qkv_tc(const float* __restrict__ X,
                                              const float* __restrict__ W) {
    __shared__ float Xs[2][32 * QXS];
    __shared__ float Ws[2][QKC * QWS];
    const u32 sbx = cvta_smem(Xs), sbw = cvta_smem(Ws);
    const int t = threadIdx.x, w = t >> 5, lane = t & 31;
    const int gid = lane >> 2, tig = lane & 3;
    const int mt = w & 1, ng = w >> 1;          // m-tile, n-group (16 cols)
    const int cb = blockIdx.x * 64;

    const float sc0 = g_scale[mt * 16 + gid];
    const float sc1 = g_scale[mt * 16 + gid + 8];

    // staging roles
    const int xm = t >> 3, xc = t & 7;          // X: 1 chunk / thread

    float acc[2][4];
#pragma unroll
    for (int nb = 0; nb < 2; nb++)
#pragma unroll
        for (int i = 0; i < 4; i++) acc[nb][i] = 0.f;

    // prologue: stage k-chunk 0 into buf 0
    cpasync16(sbx + (0 * 32 * QXS + xm * QXS + 4 * xc) * 4, &X[xm * N_ + 4 * xc]);
#pragma unroll
    for (int i = 0; i < 2; i++) {
        int idx = t + i * 256, k = idx >> 4, c4 = idx & 15;
        cpasync16(sbw + (0 * QKC * QWS + k * QWS + 4 * c4) * 4,
                  &W[(size_t)k * QKV3_ + cb + 4 * c4]);
    }
    CP_COMMIT();

    const int NST = N_ / QKC;                   // 64 stages
    for (int s = 0; s < NST; s++) {
        if (s + 1 < NST) {
            int kb = (s + 1) * QKC, b = (s + 1) & 1;
            cpasync16(sbx + (b * 32 * QXS + xm * QXS + 4 * xc) * 4,
                      &X[xm * N_ + kb + 4 * xc]);
#pragma unroll
            for (int i = 0; i < 2; i++) {
                int idx = t + i * 256, k = idx >> 4, c4 = idx & 15;
                cpasync16(sbw + (b * QKC * QWS + k * QWS + 4 * c4) * 4,
                          &W[(size_t)(kb + k) * QKV3_ + cb + 4 * c4]);
            }
            CP_COMMIT();
            CP_WAIT1();
        } else {
            CP_WAIT0();
        }
        __syncthreads();

        const float* xb = Xs[s & 1];
        const float* wb = Ws[s & 1];
#pragma unroll
        for (int k8 = 0; k8 < 4; k8++) {
            int k0 = k8 * 8;
            float xa0 = xb[(mt * 16 + gid) * QXS + k0 + tig] * sc0;
            float xa1 = xb[(mt * 16 + gid + 8) * QXS + k0 + tig] * sc1;
            float xa2 = xb[(mt * 16 + gid) * QXS + k0 + tig + 4] * sc0;
            float xa3 = xb[(mt * 16 + gid + 8) * QXS + k0 + tig + 4] * sc1;
            float ah0 = mh(xa0), al0 = xa0 - ah0;
            float ah1 = mh(xa1), al1 = xa1 - ah1;
            float ah2 = mh(xa2), al2 = xa2 - ah2;
            float ah3 = mh(xa3), al3 = xa3 - ah3;
#pragma unroll
            for (int nb = 0; nb < 2; nb++) {
                int col = ng * 16 + nb * 8 + gid;
                float w0 = wb[(k0 + tig) * QWS + col];
                float w1 = wb[(k0 + tig + 4) * QWS + col];
                float wh0 = mh(w0), wl0 = w0 - wh0;
                float wh1 = mh(w1), wl1 = w1 - wh1;
                mma8(acc[nb], ah0, ah1, ah2, ah3, wh0, wh1);
                mma8(acc[nb], ah0, ah1, ah2, ah3, wl0, wl1);
                mma8(acc[nb], al0, al1, al2, al3, wh0, wh1);
            }
        }
        __syncthreads();
    }

    // epilogue: direct stores (C frag: rows gid/gid+8, cols 2tig,2tig+1)
#pragma unroll
    for (int nb = 0; nb < 2; nb++) {
        int colg = cb + ng * 16 + nb * 8 + 2 * tig;
        *(float2*)&g_qkv[(mt * 16 + gid) * QKV3_ + colg] =
            make_float2(acc[nb][0], acc[nb][1]);
        *(float2*)&g_qkv[(mt * 16 + gid + 8) * QKV3_ + colg] =
            make_float2(acc[nb][2], acc[nb][3]);
    }
}

// ---- kernel 3: attention: bf16 QK (cp.async staged) + tf32 PV ----
// smem map (bytes):
//   0      STG  fp32 staging 34816 (K @ stride 132, V @ stride 136)
//   34816  KHI  bf16 [64][256B]    16384
//   51200  KLO  bf16 [64][256B]    16384
//   67584  QHI  bf16 [32][256B]     8192
//   75776  QLO  bf16 [32][256B]     8192
//   83968  ES   fp32 [32][68]       8704
//   92672  DEN  fp32 [32]            128
#define KST_S  132
#define VST_S  136
#define KHI_B  34816
#define KLO_B  51200
#define QHI_B  67584
#define QLO_B  75776
#define ES_F   20992
#define DEN_F  23168
#define SMEMB  92800

__global__ __launch_bounds__(256, 2) void attn_mma(
    const float* __restrict__ cK, const float* __restrict__ cV,
    const int* __restrict__ Pp)
{
    extern __shared__ float smf[];
    char* smb = (char*)smf;
    const u32 sb = cvta_smem(smf);
    const int t = threadIdx.x, w = t >> 5, lane = t & 31;
    const int gid = lane >> 2, tig = lane & 3;
    const int h = blockIdx.y, c = blockIdx.x, P = *Pp;
    const int kg = w >> 1, qh = w & 1;
    const int kb = kg * 16, qb = qh * 16;

    const float* Kh = cK + (size_t)h * L_ * D_;
    const float* Vh = cV + (size_t)h * L_ * D_;

    // ---- stage Q bf16 hi/lo (swizzled) ----
    {
        int q = t >> 3, c2 = t & 7;
#pragma unroll
        for (int i = 0; i < 2; i++) {
            int ch = 2 * c2 + i;
            const float* src = &g_qkv[q * QKV3_ + h * D_ + 8 * ch];
            float4 x = *(const float4*)src;
            float4 y = *(const float4*)(src + 4);
            u32 sw = (u32)(q * 256 + ((ch ^ (q & 7)) << 4));
            *(uint4*)(smb + QHI_B + sw) =
                make_uint4(bpack(x.x, x.y), bpack(x.z, x.w), bpack(y.x, y.y), bpack(y.z, y.w));
            float l0 = x.x - bh(x.x), l1 = x.y - bh(x.y), l2 = x.z - bh(x.z), l3 = x.w - bh(x.w);
            float l4 = y.x - bh(y.x), l5 = y.y - bh(y.y), l6 = y.z - bh(y.z), l7 = y.w - bh(y.w);
            *(uint4*)(smb + QLO_B + sw) =
                make_uint4(bpack(l0, l1), bpack(l2, l3), bpack(l4, l5), bpack(l6, l7));
        }
    }
    if (t < 32) smf[DEN_F + t] = 0.f;

    float o[2][2][4];
#pragma unroll
    for (int a = 0; a < 2; a++)
#pragma unroll
        for (int b = 0; b < 2; b++)
#pragma unroll
            for (int k = 0; k < 4; k++) o[a][b][k] = 0.f;

    // ldmatrix per-lane address bases
    const int subm = lane >> 3;
    const int rowA = kb + (lane & 7) + ((subm & 1) << 3);
    const int chA  = subm >> 1;
    const int rowB0 = qb + (lane & 7);
    const int chB  = (lane >> 3) & 1;

    // prologue: stage K(0) (stride 132)
    {
        int l0 = c * CHUNK_;
#pragma unroll
        for (int i = 0; i < 8; i++) {
            int idx = t + i * 256, row = idx >> 5, c4 = idx & 31;
            cpasync16(sb + (row * KST_S + 4 * c4) * 4, &Kh[(size_t)(l0 + row) * D_ + 4 * c4]);
        }
        CP_COMMIT();
    }

    for (int s = 0; s < NSUB_; s++) {
        const int l0 = c * CHUNK_ + s * SK_;
        CP_WAIT0();
        __syncthreads();                      // K(s) staged

        // fresh K rows (stride 132)
        {
            int lo_ = l0 > P ? l0 : P;
            int hi_ = (l0 + SK_) < (P + M_) ? (l0 + SK_) : (P + M_);
            if (lo_ < hi_) {
                for (int idx = t; idx < (hi_ - lo_) * 32; idx += 256) {
                    int r = idx >> 5, c4 = idx & 31;
                    int gl = lo_ + r;
                    *(float4*)&smf[(gl - l0) * KST_S + 4 * c4] =
                        *(const float4*)&g_qkv[(gl - P) * QKV3_ + N_ + h * D_ + 4 * c4];
                }
                __syncthreads();
            }
        }

        // ---- convert K -> KHI/KLO bf16 (swizzled) ----
        {
            int row = t >> 2, c4 = t & 3;
            const float* src = smf + row * KST_S;
            char* hid = smb + KHI_B + row * 256;
            char* lod = smb + KLO_B + row * 256;
#pragma unroll
            for (int i = 0; i < 4; i++) {
                int ch = 4 * c4 + i;
                float4 x = *(const float4*)(src + 8 * ch);
                float4 y = *(const float4*)(src + 8 * ch + 4);
                u32 sw = (u32)((ch ^ (row & 7)) << 4);
                *(uint4*)(hid + sw) =
                    make_uint4(bpack(x.x, x.y), bpack(x.z, x.w), bpack(y.x, y.y), bpack(y.z, y.w));
                float l0f = x.x - bh(x.x), l1f = x.y - bh(x.y), l2f = x.z - bh(x.z), l3f = x.w - bh(x.w);
                float l4f = y.x - bh(y.x), l5f = y.y - bh(y.y), l6f = y.z - bh(y.z), l7f = y.w - bh(y.w);
                *(uint4*)(lod + sw) =
                    make_uint4(bpack(l0f, l1f), bpack(l2f, l3f), bpack(l4f, l5f), bpack(l6f, l7f));
            }
        }
        __syncthreads();                      // K bf16 ready; staging free

        // stage V(s) into staging (stride 136)
#pragma unroll
        for (int i = 0; i < 8; i++) {
            int idx = t + i * 256, row = idx >> 5, c4 = idx & 31;
            cpasync16(sb + (row * VST_S + 4 * c4) * 4, &Vh[(size_t)(l0 + row) * D_ + 4 * c4]);
        }
        CP_COMMIT();

        // ---- QK: bf16 3-pass, ldmatrix operands ----
        float sc[2][4];
#pragma unroll
        for (int j = 0; j < 2; j++)
#pragma unroll
            for (int k = 0; k < 4; k++) sc[j][k] = 0.f;
#pragma unroll
        for (int ks = 0; ks < 8; ks++) {
            u32 ka0, ka1, ka2, ka3, kl0, kl1, kl2, kl3;
            u32 swA = (u32)(rowA * 256 + (((2 * ks + chA) ^ (rowA & 7)) << 4));
            ldsm4(ka0, ka1, ka2, ka3, sb + KHI_B + swA);
            ldsm4(kl0, kl1, kl2, kl3, sb + KLO_B + swA);
#pragma unroll
            for (int j2 = 0; j2 < 2; j2++) {
                int rowB = rowB0 + j2 * 8;
                u32 swB = (u32)(rowB * 256 + (((2 * ks + chB) ^ (rowB & 7)) << 4));
                u32 qh0, qh1, ql0, ql1;
                ldsm2(qh0, qh1, sb + QHI_B + swB);
                ldsm2(ql0, ql1, sb + QLO_B + swB);
                mma16(sc[j2], ka0, ka1, ka2, ka3, qh0, qh1);
                mma16(sc[j2], kl0, kl1, kl2, kl3, qh0, qh1);
                mma16(sc[j2], ka0, ka1, ka2, ka3, ql0, ql1);
            }
        }

        // ---- exp (tf32-mask) -> ES, denominators ----
#pragma unroll
        for (int j2 = 0; j2 < 2; j2++) {
            float e0 = mh(__expf(sc[j2][0]));
            float e1 = mh(__expf(sc[j2][1]));
            float e2 = mh(__expf(sc[j2][2]));
            float e3 = mh(__expf(sc[j2][3]));
            int q0 = qb + j2 * 8 + 2 * tig;
            smf[ES_F + q0 * 68 + kb + gid]           = e0;
            smf[ES_F + (q0 + 1) * 68 + kb + gid]     = e1;
            smf[ES_F + q0 * 68 + kb + gid + 8]       = e2;
            smf[ES_F + (q0 + 1) * 68 + kb + gid + 8] = e3;
            float s0 = e0 + e2, s1 = e1 + e3;
#pragma unroll
            for (int off = 4; off < 32; off <<= 1) {
                s0 += __shfl_xor_sync(0xffffffffu, s0, off);
                s1 += __shfl_xor_sync(0xffffffffu, s1, off);
            }
            if (lane < 4) {
                atomicAdd(&smf[DEN_F + q0], s0);
                atomicAdd(&smf[DEN_F + q0 + 1], s1);
            }
        }

        CP_WAIT0();
        __syncthreads();                      // V staged + ES visible

        // fresh V rows (stride 136)
        {
            int lo_ = l0 > P ? l0 : P;
            int hi_ = (l0 + SK_) < (P + M_) ? (l0 + SK_) : (P + M_);
            if (lo_ < hi_) {
                for (int idx = t; idx < (hi_ - lo_) * 32; idx += 256) {
                    int r = idx >> 5, c4 = idx & 31;
                    int gl = lo_ + r;
                    *(float4*)&smf[(gl - l0) * VST_S + 4 * c4] =
                        *(const float4*)&g_qkv[(gl - P) * QKV3_ + 2 * N_ + h * D_ + 4 * c4];
                }
                __syncthreads();
            }
        }

        // ---- PV: E (tf32-rounded) x V (hi/lo mask 2-pass, tf32) ----
#pragma unroll 2
        for (int ks = 0; ks < 8; ks++) {
            int l = ks * 8;
            float a0[4], a1[4];
            a0[0] = smf[ES_F + gid * 68 + l + tig];
            a0[1] = smf[ES_F + (gid + 8) * 68 + l + tig];
            a0[2] = smf[ES_F + gid * 68 + l + tig + 4];
            a0[3] = smf[ES_F + (gid + 8) * 68 + l + tig + 4];
            a1[0] = smf[ES_F + (16 + gid) * 68 + l + tig];
            a1[1] = smf[ES_F + (24 + gid) * 68 + l + tig];
            a1[2] = smf[ES_F + (16 + gid) * 68 + l + tig + 4];
            a1[3] = smf[ES_F + (24 + gid) * 68 + l + tig + 4];
#pragma unroll
            for (int nb = 0; nb < 2; nb++) {
                int d = w * 16 + nb * 8 + gid;
                float v0 = smf[(l + tig) * VST_S + d];
                float v1 = smf[(l + tig + 4) * VST_S + d];
                float bh0 = mh(v0), bl0 = v0 - bh0;
                float bh1 = mh(v1), bl1 = v1 - bh1;
                mma8(o[0][nb], a0[0], a0[1], a0[2], a0[3], bh0, bh1);
                mma8(o[0][nb], a0[0], a0[1], a0[2], a0[3], bl0, bl1);
                mma8(o[1][nb], a1[0], a1[1], a1[2], a1[3], bh0, bh1);
                mma8(o[1][nb], a1[0], a1[1], a1[2], a1[3], bl0, bl1);
            }
        }
        __syncthreads();                      // staging/ES consumed

        if (s + 1 < NSUB_) {                  // stage K(s+1) (stride 132)
            int ln = l0 + SK_;
#pragma unroll
            for (int i = 0; i < 8; i++) {
                int idx = t + i * 256, row = idx >> 5, c4 = idx & 31;
                cpasync16(sb + (row * KST_S + 4 * c4) * 4, &Kh[(size_t)(ln + row) * D_ + 4 * c4]);
            }
            CP_COMMIT();
        }
    }

    // ---- epilogue ----
    const size_t base = (size_t)(h * NC_ + c) * M_ * D_;
#pragma unroll
    for (int mt = 0; mt < 2; mt++)
#pragma unroll
        for (int nb = 0; nb < 2; nb++) {
            int q0 = mt * 16 + gid, d0 = w * 16 + nb * 8 + 2 * tig;
            *(float2*)&g_num[base + (size_t)q0 * D_ + d0] =
                make_float2(o[mt][nb][0], o[mt][nb][1]);
            *(float2*)&g_num[base + (size_t)(q0 + 8) * D_ + d0] =
                make_float2(o[mt][nb][2], o[mt][nb][3]);
        }
    if (t < 32) g_den[(h * NC_ + c) * M_ + t] = smf[DEN_F + t];
}

// ---- kernel 4: reduce ----
__global__ void reduce_out(float* __restrict__ out) {
    int hm = blockIdx.x, h = hm >> 5, m = hm & 31;
    int d = threadIdx.x;
    float dsum = 0.f, nsum = 0.f;
#pragma unroll 8
    for (int c = 0; c < NC_; c++) dsum += g_den[(h * NC_ + c) * M_ + m];
#pragma unroll 8
    for (int c = 0; c < NC_; c++)
        nsum += g_num[((size_t)(h * NC_ + c) * M_ + m) * D_ + d];
    out[m * N_ + h * D_ + d] = nsum / dsum;
}

extern "C" void kernel_launch(void* const* d_in, const int* in_sizes, int n_in,
                              void* d_out, int out_size) {
    const float* X  = (const float*)d_in[0];
    const float* W  = (const float*)d_in[1];
    const float* cK = (const float*)d_in[2];
    const float* cV = (const float*)d_in[3];
    const int*   P  = (const int*)d_in[4];
    float* out = (float*)d_out;

    cudaFuncSetAttribute(attn_mma, cudaFuncAttributeMaxDynamicSharedMemorySize, SMEMB);

    rms_kernel<<<M_, 256>>>(X);
    qkv_tc<<<QKV3_ / 64, 256>>>(X, W);
    attn_mma<<<dim3(NC_, H_), 256, SMEMB>>>(cK, cV, P);
    reduce_out<<<H_ * M_, 128>>>(out);
}

// round 14
// speedup vs baseline: 1.0285x; 1.0285x over previous
#include <cuda_runtime.h>
#include <cstdint>

#define M_     32
#define N_     2048
#define D_     128
#define L_     32768
#define H_     16
#define QKV3_  6144
#define CHUNK_ 1024
#define NC_    32
#define SK_    64          // keys per subtile
#define NSUB_  16          // CHUNK_/SK_

typedef unsigned long long u64;
typedef unsigned int u32;

__device__ float g_scale[M_];
__device__ float g_qkv[M_ * QKV3_];
__device__ float g_num[H_ * NC_ * M_ * D_];   // [hc][q][d]
__device__ float g_den[H_ * NC_ * M_];

// ---- helpers ----
// tf32 "hi" mask (13-bit mantissa)
__device__ __forceinline__ float mh(float x) {
    return __uint_as_float(__float_as_uint(x) & 0xFFFFE000u);
}
// bf16 "hi" mask (truncation)
__device__ __forceinline__ float bh(float x) {
    return __uint_as_float(__float_as_uint(x) & 0xFFFF0000u);
}
// pack two floats' bf16 truncations
__device__ __forceinline__ u32 bpack(float a, float b) {
    u32 r;
    asm("prmt.b32 %0, %1, %2, 0x7632;" : "=r"(r)
        : "r"(__float_as_uint(a)), "r"(__float_as_uint(b)));
    return r;
}
__device__ __forceinline__ u32 cvta_smem(const void* p) {
    u32 a; asm("{ .reg .u64 t; cvta.to.shared.u64 t, %1; cvt.u32.u64 %0, t; }" : "=r"(a) : "l"(p)); return a;
}
__device__ __forceinline__ void cpasync16(u32 s, const void* g) {
    asm volatile("cp.async.cg.shared.global [%0], [%1], 16;" :: "r"(s), "l"(g));
}
#define CP_COMMIT() asm volatile("cp.async.commit_group;" ::: "memory")
#define CP_WAIT0()  asm volatile("cp.async.wait_group 0;" ::: "memory")
#define CP_WAIT1()  asm volatile("cp.async.wait_group 1;" ::: "memory")
#define CP_WAIT2()  asm volatile("cp.async.wait_group 2;" ::: "memory")

__device__ __forceinline__ void ldsm4(u32& r0, u32& r1, u32& r2, u32& r3, u32 a) {
    asm volatile("ldmatrix.sync.aligned.m8n8.x4.shared.b16 {%0,%1,%2,%3}, [%4];"
        : "=r"(r0), "=r"(r1), "=r"(r2), "=r"(r3) : "r"(a));
}
__device__ __forceinline__ void ldsm2(u32& r0, u32& r1, u32 a) {
    asm volatile("ldmatrix.sync.aligned.m8n8.x2.shared.b16 {%0,%1}, [%2];"
        : "=r"(r0), "=r"(r1) : "r"(a));
}
// bf16 m16n8k16
__device__ __forceinline__ void mma16(float* c, u32 a0, u32 a1, u32 a2, u32 a3,
                                      u32 b0, u32 b1) {
    asm volatile("mma.sync.aligned.m16n8k16.row.col.f32.bf16.bf16.f32 "
        "{%0,%1,%2,%3}, {%4,%5,%6,%7}, {%8,%9}, {%0,%1,%2,%3};"
        : "+f"(c[0]), "+f"(c[1]), "+f"(c[2]), "+f"(c[3])
        : "r"(a0), "r"(a1), "r"(a2), "r"(a3), "r"(b0), "r"(b1));
}
// tf32 m16n8k8
__device__ __forceinline__ void mma8(float* c, float a0, float a1, float a2, float a3,
                                     float b0, float b1) {
    asm volatile("mma.sync.aligned.m16n8k8.row.col.f32.tf32.tf32.f32 "
        "{%0,%1,%2,%3}, {%4,%5,%6,%7}, {%8,%9}, {%0,%1,%2,%3};"
        : "+f"(c[0]), "+f"(c[1]), "+f"(c[2]), "+f"(c[3])
        : "r"(__float_as_uint(a0)), "r"(__float_as_uint(a1)),
          "r"(__float_as_uint(a2)), "r"(__float_as_uint(a3)),
          "r"(__float_as_uint(b0)), "r"(__float_as_uint(b1)));
}

// ---- kernel 1: RMS scales ----
__global__ void rms_kernel(const float* __restrict__ X) {
    int m = blockIdx.x;
    float s = 0.f;
    for (int k = threadIdx.x; k < N_; k += 256) { float v = X[m * N_ + k]; s += v * v; }
    __shared__ float red[256];
    red[threadIdx.x] = s; __syncthreads();
    for (int o = 128; o > 0; o >>= 1) {
        if (threadIdx.x < o) red[threadIdx.x] += red[threadIdx.x + o];
        __syncthreads();
    }
    if (threadIdx.x == 0) g_scale[m] = rsqrtf(red[0] * (1.0f / N_));
}

// ---- kernel 2: QKV GEMM via tf32 mma 3-pass, 3-deep cp.async pipeline ----
#define QKC 32
#define QXS 36
#define QWS 72
#define QPIPE 3
__global__ __launch_bounds__(256) void qkv_tc(const float* __restrict__ X,
                                              const float* __restrict__ W) {
    __shared__ float Xs[QPIPE][32 * QXS];     // 13.8 KB
    __shared__ float Ws[QPIPE][QKC * QWS];    // 27.6 KB
    const u32 sbx = cvta_smem(Xs), sbw = cvta_smem(Ws);
    const int t = threadIdx.x, w = t >> 5, lane = t & 31;
    const int gid = lane >> 2, tig = lane & 3;
    const int mt = w & 1, ng = w >> 1;        // m-tile, n-group (16 cols)
    const int cb = blockIdx.x * 64;

    const float sc0 = g_scale[mt * 16 + gid];
    const float sc1 = g_scale[mt * 16 + gid + 8];

    const int xm = t >> 3, xc = t & 7;        // X staging role
    const int wk = t >> 4, wc = t & 15;       // W staging role (2 iters)

    float acc[2][4];
#pragma unroll
    for (int nb = 0; nb < 2; nb++)
#pragma unroll
        for (int i = 0; i < 4; i++) acc[nb][i] = 0.f;

    const int NST = N_ / QKC;                 // 64 stages

    // stage helper (inlined twice)
#define QSTAGE(S, BUF) do {                                                   \
        int kb_ = (S) * QKC;                                                  \
        cpasync16(sbx + ((BUF) * 32 * QXS + xm * QXS + 4 * xc) * 4,           \
                  &X[xm * N_ + kb_ + 4 * xc]);                                \
        cpasync16(sbw + ((BUF) * QKC * QWS + wk * QWS + 4 * wc) * 4,          \
                  &W[(size_t)(kb_ + wk) * QKV3_ + cb + 4 * wc]);              \
        cpasync16(sbw + ((BUF) * QKC * QWS + (wk + 16) * QWS + 4 * wc) * 4,   \
                  &W[(size_t)(kb_ + wk + 16) * QKV3_ + cb + 4 * wc]);         \
        CP_COMMIT();                                                          \
    } while (0)

    QSTAGE(0, 0);
    QSTAGE(1, 1);

    for (int s = 0; s < NST; s++) {
        __syncthreads();                      // everyone done with buf (s-1)%3
        if (s + 2 < NST) QSTAGE(s + 2, (s + 2) % QPIPE);
        if (s < NST - 2) { CP_WAIT2(); }
        else if (s == NST - 2) { CP_WAIT1(); }
        else { CP_WAIT0(); }
        __syncthreads();                      // stage s visible to all

        const float* xb = Xs[s % QPIPE];
        const float* wb = Ws[s % QPIPE];
#pragma unroll
        for (int k8 = 0; k8 < 4; k8++) {
            int k0 = k8 * 8;
            float xa0 = xb[(mt * 16 + gid) * QXS + k0 + tig] * sc0;
            float xa1 = xb[(mt * 16 + gid + 8) * QXS + k0 + tig] * sc1;
            float xa2 = xb[(mt * 16 + gid) * QXS + k0 + tig + 4] * sc0;
            float xa3 = xb[(mt * 16 + gid + 8) * QXS + k0 + tig + 4] * sc1;
            float ah0 = mh(xa0), al0 = xa0 - ah0;
            float ah1 = mh(xa1), al1 = xa1 - ah1;
            float ah2 = mh(xa2), al2 = xa2 - ah2;
            float ah3 = mh(xa3), al3 = xa3 - ah3;
#pragma unroll
            for (int nb = 0; nb < 2; nb++) {
                int col = ng * 16 + nb * 8 + gid;
                float w0 = wb[(k0 + tig) * QWS + col];
                float w1 = wb[(k0 + tig + 4) * QWS + col];
                float wh0 = mh(w0), wl0 = w0 - wh0;
                float wh1 = mh(w1), wl1 = w1 - wh1;
                mma8(acc[nb], ah0, ah1, ah2, ah3, wh0, wh1);
                mma8(acc[nb], ah0, ah1, ah2, ah3, wl0, wl1);
                mma8(acc[nb], al0, al1, al2, al3, wh0, wh1);
            }
        }
    }

#pragma unroll
    for (int nb = 0; nb < 2; nb++) {
        int colg = cb + ng * 16 + nb * 8 + 2 * tig;
        *(float2*)&g_qkv[(mt * 16 + gid) * QKV3_ + colg] =
            make_float2(acc[nb][0], acc[nb][1]);
        *(float2*)&g_qkv[(mt * 16 + gid + 8) * QKV3_ + colg] =
            make_float2(acc[nb][2], acc[nb][3]);
    }
}

// ---- kernel 3: attention: bf16 QK (cp.async staged) + tf32 PV ----
// smem map (bytes):
//   0      STG  fp32 staging 34816 (K @ stride 132, V @ stride 136)
//   34816  KHI  bf16 [64][256B]    16384
//   51200  KLO  bf16 [64][256B]    16384
//   67584  QHI  bf16 [32][256B]     8192
//   75776  QLO  bf16 [32][256B]     8192
//   83968  ES   fp32 [32][68]       8704
//   92672  DEN  fp32 [32]            128
#define KST_S  132
#define VST_S  136
#define KHI_B  34816
#define KLO_B  51200
#define QHI_B  67584
#define QLO_B  75776
#define ES_F   20992
#define DEN_F  23168
#define SMEMB  92800

__global__ __launch_bounds__(256, 2) void attn_mma(
    const float* __restrict__ cK, const float* __restrict__ cV,
    const int* __restrict__ Pp)
{
    extern __shared__ float smf[];
    char* smb = (char*)smf;
    const u32 sb = cvta_smem(smf);
    const int t = threadIdx.x, w = t >> 5, lane = t & 31;
    const int gid = lane >> 2, tig = lane & 3;
    const int h = blockIdx.y, c = blockIdx.x, P = *Pp;
    const int kg = w >> 1, qh = w & 1;
    const int kb = kg * 16, qb = qh * 16;

    const float* Kh = cK + (size_t)h * L_ * D_;
    const float* Vh = cV + (size_t)h * L_ * D_;

    // ---- stage Q bf16 hi/lo (swizzled) ----
    {
        int q = t >> 3, c2 = t & 7;
#pragma unroll
        for (int i = 0; i < 2; i++) {
            int ch = 2 * c2 + i;
            const float* src = &g_qkv[q * QKV3_ + h * D_ + 8 * ch];
            float4 x = *(const float4*)src;
            float4 y = *(const float4*)(src + 4);
            u32 sw = (u32)(q * 256 + ((ch ^ (q & 7)) << 4));
            *(uint4*)(smb + QHI_B + sw) =
                make_uint4(bpack(x.x, x.y), bpack(x.z, x.w), bpack(y.x, y.y), bpack(y.z, y.w));
            float l0 = x.x - bh(x.x), l1 = x.y - bh(x.y), l2 = x.z - bh(x.z), l3 = x.w - bh(x.w);
            float l4 = y.x - bh(y.x), l5 = y.y - bh(y.y), l6 = y.z - bh(y.z), l7 = y.w - bh(y.w);
            *(uint4*)(smb + QLO_B + sw) =
                make_uint4(bpack(l0, l1), bpack(l2, l3), bpack(l4, l5), bpack(l6, l7));
        }
    }
    if (t < 32) smf[DEN_F + t] = 0.f;

    float o[2][2][4];
#pragma unroll
    for (int a = 0; a < 2; a++)
#pragma unroll
        for (int b = 0; b < 2; b++)
#pragma unroll
            for (int k = 0; k < 4; k++) o[a][b][k] = 0.f;

    // ldmatrix per-lane address bases
    const int subm = lane >> 3;
    const int rowA = kb + (lane & 7) + ((subm & 1) << 3);
    const int chA  = subm >> 1;
    const int rowB0 = qb + (lane & 7);
    const int chB  = (lane >> 3) & 1;

    // prologue: stage K(0) (stride 132)
    {
        int l0 = c * CHUNK_;
#pragma unroll
        for (int i = 0; i < 8; i++) {
            int idx = t + i * 256, row = idx >> 5, c4 = idx & 31;
            cpasync16(sb + (row * KST_S + 4 * c4) * 4, &Kh[(size_t)(l0 + row) * D_ + 4 * c4]);
        }
        CP_COMMIT();
    }

    for (int s = 0; s < NSUB_; s++) {
        const int l0 = c * CHUNK_ + s * SK_;
        CP_WAIT0();
        __syncthreads();                      // K(s) staged

        // fresh K rows (stride 132)
        {
            int lo_ = l0 > P ? l0 : P;
            int hi_ = (l0 + SK_) < (P + M_) ? (l0 + SK_) : (P + M_);
            if (lo_ < hi_) {
                for (int idx = t; idx < (hi_ - lo_) * 32; idx += 256) {
                    int r = idx >> 5, c4 = idx & 31;
                    int gl = lo_ + r;
                    *(float4*)&smf[(gl - l0) * KST_S + 4 * c4] =
                        *(const float4*)&g_qkv[(gl - P) * QKV3_ + N_ + h * D_ + 4 * c4];
                }
                __syncthreads();
            }
        }

        // ---- convert K -> KHI/KLO bf16 (swizzled) ----
        {
            int row = t >> 2, c4 = t & 3;
            const float* src = smf + row * KST_S;
            char* hid = smb + KHI_B + row * 256;
            char* lod = smb + KLO_B + row * 256;
#pragma unroll
            for (int i = 0; i < 4; i++) {
                int ch = 4 * c4 + i;
                float4 x = *(const float4*)(src + 8 * ch);
                float4 y = *(const float4*)(src + 8 * ch + 4);
                u32 sw = (u32)((ch ^ (row & 7)) << 4);
                *(uint4*)(hid + sw) =
                    make_uint4(bpack(x.x, x.y), bpack(x.z, x.w), bpack(y.x, y.y), bpack(y.z, y.w));
                float l0f = x.x - bh(x.x), l1f = x.y - bh(x.y), l2f = x.z - bh(x.z), l3f = x.w - bh(x.w);
                float l4f = y.x - bh(y.x), l5f = y.y - bh(y.y), l6f = y.z - bh(y.z), l7f = y.w - bh(y.w);
                *(uint4*)(lod + sw) =
                    make_uint4(bpack(l0f, l1f), bpack(l2f, l3f), bpack(l4f, l5f), bpack(l6f, l7f));
            }
        }
        __syncthreads();                      // K bf16 ready; staging free

        // stage V(s) into staging (stride 136)
#pragma unroll
        for (int i = 0; i < 8; i++) {
            int idx = t + i * 256, row = idx >> 5, c4 = idx & 31;
            cpasync16(sb + (row * VST_S + 4 * c4) * 4, &Vh[(size_t)(l0 + row) * D_ + 4 * c4]);
        }
        CP_COMMIT();

        // ---- QK: bf16 3-pass, ldmatrix operands ----
        float sc[2][4];
#pragma unroll
        for (int j = 0; j < 2; j++)
#pragma unroll
            for (int k = 0; k < 4; k++) sc[j][k] = 0.f;
#pragma unroll
        for (int ks = 0; ks < 8; ks++) {
            u32 ka0, ka1, ka2, ka3, kl0, kl1, kl2, kl3;
            u32 swA = (u32)(rowA * 256 + (((2 * ks + chA) ^ (rowA & 7)) << 4));
            ldsm4(ka0, ka1, ka2, ka3, sb + KHI_B + swA);
            ldsm4(kl0, kl1, kl2, kl3, sb + KLO_B + swA);
#pragma unroll
            for (int j2 = 0; j2 < 2; j2++) {
                int rowB = rowB0 + j2 * 8;
                u32 swB = (u32)(rowB * 256 + (((2 * ks + chB) ^ (rowB & 7)) << 4));
                u32 qh0, qh1, ql0, ql1;
                ldsm2(qh0, qh1, sb + QHI_B + swB);
                ldsm2(ql0, ql1, sb + QLO_B + swB);
                mma16(sc[j2], ka0, ka1, ka2, ka3, qh0, qh1);
                mma16(sc[j2], kl0, kl1, kl2, kl3, qh0, qh1);
                mma16(sc[j2], ka0, ka1, ka2, ka3, ql0, ql1);
            }
        }

        // ---- exp (tf32-mask) -> ES, denominators ----
#pragma unroll
        for (int j2 = 0; j2 < 2; j2++) {
            float e0 = mh(__expf(sc[j2][0]));
            float e1 = mh(__expf(sc[j2][1]));
            float e2 = mh(__expf(sc[j2][2]));
            float e3 = mh(__expf(sc[j2][3]));
            int q0 = qb + j2 * 8 + 2 * tig;
            smf[ES_F + q0 * 68 + kb + gid]           = e0;
            smf[ES_F + (q0 + 1) * 68 + kb + gid]     = e1;
            smf[ES_F + q0 * 68 + kb + gid + 8]       = e2;
            smf[ES_F + (q0 + 1) * 68 + kb + gid + 8] = e3;
            float s0 = e0 + e2, s1 = e1 + e3;
#pragma unroll
            for (int off = 4; off < 32; off <<= 1) {
                s0 += __shfl_xor_sync(0xffffffffu, s0, off);
                s1 += __shfl_xor_sync(0xffffffffu, s1, off);
            }
            if (lane < 4) {
                atomicAdd(&smf[DEN_F + q0], s0);
                atomicAdd(&smf[DEN_F + q0 + 1], s1);
            }
        }

        CP_WAIT0();
        __syncthreads();                      // V staged + ES visible

        // fresh V rows (stride 136)
        {
            int lo_ = l0 > P ? l0 : P;
            int hi_ = (l0 + SK_) < (P + M_) ? (l0 + SK_) : (P + M_);
            if (lo_ < hi_) {
                for (int idx = t; idx < (hi_ - lo_) * 32; idx += 256) {
                    int r = idx >> 5, c4 = idx & 31;
                    int gl = lo_ + r;
                    *(float4*)&smf[(gl - l0) * VST_S + 4 * c4] =
                        *(const float4*)&g_qkv[(gl - P) * QKV3_ + 2 * N_ + h * D_ + 4 * c4];
                }
                __syncthreads();
            }
        }

        // ---- PV: E (tf32-rounded) x V (hi/lo mask 2-pass, tf32) ----
#pragma unroll 2
        for (int ks = 0; ks < 8; ks++) {
            int l = ks * 8;
            float a0[4], a1[4];
            a0[0] = smf[ES_F + gid * 68 + l + tig];
            a0[1] = smf[ES_F + (gid + 8) * 68 + l + tig];
            a0[2] = smf[ES_F + gid * 68 + l + tig + 4];
            a0[3] = smf[ES_F + (gid + 8) * 68 + l + tig + 4];
            a1[0] = smf[ES_F + (16 + gid) * 68 + l + tig];
            a1[1] = smf[ES_F + (24 + gid) * 68 + l + tig];
            a1[2] = smf[ES_F + (16 + gid) * 68 + l + tig + 4];
            a1[3] = smf[ES_F + (24 + gid) * 68 + l + tig + 4];
#pragma unroll
            for (int nb = 0; nb < 2; nb++) {
                int d = w * 16 + nb * 8 + gid;
                float v0 = smf[(l + tig) * VST_S + d];
                float v1 = smf[(l + tig + 4) * VST_S + d];
                float bh0 = mh(v0), bl0 = v0 - bh0;
                float bh1 = mh(v1), bl1 = v1 - bh1;
                mma8(o[0][nb], a0[0], a0[1], a0[2], a0[3], bh0, bh1);
                mma8(o[0][nb], a0[0], a0[1], a0[2], a0[3], bl0, bl1);
                mma8(o[1][nb], a1[0], a1[1], a1[2], a1[3], bh0, bh1);
                mma8(o[1][nb], a1[0], a1[1], a1[2], a1[3], bl0, bl1);
            }
        }
        __syncthreads();                      // staging/ES consumed

        if (s + 1 < NSUB_) {                  // stage K(s+1) (stride 132)
            int ln = l0 + SK_;
#pragma unroll
            for (int i = 0; i < 8; i++) {
                int idx = t + i * 256, row = idx >> 5, c4 = idx & 31;
                cpasync16(sb + (row * KST_S + 4 * c4) * 4, &Kh[(size_t)(ln + row) * D_ + 4 * c4]);
            }
            CP_COMMIT();
        }
    }

    // ---- epilogue ----
    const size_t base = (size_t)(h * NC_ + c) * M_ * D_;
#pragma unroll
    for (int mt = 0; mt < 2; mt++)
#pragma unroll
        for (int nb = 0; nb < 2; nb++) {
            int q0 = mt * 16 + gid, d0 = w * 16 + nb * 8 + 2 * tig;
            *(float2*)&g_num[base + (size_t)q0 * D_ + d0] =
                make_float2(o[mt][nb][0], o[mt][nb][1]);
            *(float2*)&g_num[base + (size_t)(q0 + 8) * D_ + d0] =
                make_float2(o[mt][nb][2], o[mt][nb][3]);
        }
    if (t < 32) g_den[(h * NC_ + c) * M_ + t] = smf[DEN_F + t];
}

// ---- kernel 4: reduce (chunk dim parallelized 4-way) ----
__global__ __launch_bounds__(512) void reduce_out(float* __restrict__ out) {
    __shared__ float part[512];
    int hm = blockIdx.x, h = hm >> 5, m = hm & 31;
    int t = threadIdx.x, d = t & 127, cg = t >> 7;   // 4 chunk-groups
    float nsum = 0.f;
#pragma unroll 8
    for (int i = 0; i < 8; i++) {
        int c = cg * 8 + i;
        nsum += g_num[((size_t)(h * NC_ + c) * M_ + m) * D_ + d];
    }
    part[t] = nsum;
    __syncthreads();
    if (t < 128) {
        float tot = part[t] + part[t + 128] + part[t + 256] + part[t + 384];
        float dsum = 0.f;
#pragma unroll 8
        for (int c = 0; c < NC_; c++) dsum += g_den[(h * NC_ + c) * M_ + m];
        out[m * N_ + h * D_ + d] = tot / dsum;
    }
}

extern "C" void kernel_launch(void* const* d_in, const int* in_sizes, int n_in,
                              void* d_out, int out_size) {
    const float* X  = (const float*)d_in[0];
    const float* W  = (const float*)d_in[1];
    const float* cK = (const float*)d_in[2];
    const float* cV = (const float*)d_in[3];
    const int*   P  = (const int*)d_in[4];
    float* out = (float*)d_out;

    cudaFuncSetAttribute(attn_mma, cudaFuncAttributeMaxDynamicSharedMemorySize, SMEMB);

    rms_kernel<<<M_, 256>>>(X);
    qkv_tc<<<QKV3_ / 64, 256>>>(X, W);
    attn_mma<<<dim3(NC_, H_), 256, SMEMB>>>(cK, cV, P);
    reduce_out<<<H_ * M_, 512>>>(out);
}

// round 15
// speedup vs baseline: 1.1490x; 1.1172x over previous
#include <cuda_runtime.h>
#include <cstdint>

#define M_     32
#define N_     2048
#define D_     128
#define L_     32768
#define H_     16
#define QKV3_  6144
#define SK_    64          // keys per subtile
#define NCC_   37          // chunks (31x14 + 6x13 subtiles = 512)

typedef unsigned long long u64;
typedef unsigned int u32;

__device__ float g_scale[M_];
__device__ float g_qkv[M_ * QKV3_];
__device__ float g_qkvB[M_ * QKV3_];
__device__ float g_num[H_ * NCC_ * M_ * D_];
__device__ float g_den[H_ * NCC_ * M_];

// ---- helpers ----
__device__ __forceinline__ float mh(float x) {
    return __uint_as_float(__float_as_uint(x) & 0xFFFFE000u);
}
__device__ __forceinline__ float bh(float x) {
    return __uint_as_float(__float_as_uint(x) & 0xFFFF0000u);
}
__device__ __forceinline__ u32 bpack(float a, float b) {
    u32 r;
    asm("prmt.b32 %0, %1, %2, 0x7632;" : "=r"(r)
        : "r"(__float_as_uint(a)), "r"(__float_as_uint(b)));
    return r;
}
__device__ __forceinline__ u32 cvta_smem(const void* p) {
    u32 a; asm("{ .reg .u64 t; cvta.to.shared.u64 t, %1; cvt.u32.u64 %0, t; }" : "=r"(a) : "l"(p)); return a;
}
__device__ __forceinline__ void cpasync16(u32 s, const void* g) {
    asm volatile("cp.async.cg.shared.global [%0], [%1], 16;" :: "r"(s), "l"(g));
}
#define CP_COMMIT() asm volatile("cp.async.commit_group;" ::: "memory")
#define CP_WAIT0()  asm volatile("cp.async.wait_group 0;" ::: "memory")
#define CP_WAIT1()  asm volatile("cp.async.wait_group 1;" ::: "memory")
#define CP_WAIT2()  asm volatile("cp.async.wait_group 2;" ::: "memory")

__device__ __forceinline__ void ldsm4(u32& r0, u32& r1, u32& r2, u32& r3, u32 a) {
    asm volatile("ldmatrix.sync.aligned.m8n8.x4.shared.b16 {%0,%1,%2,%3}, [%4];"
        : "=r"(r0), "=r"(r1), "=r"(r2), "=r"(r3) : "r"(a));
}
__device__ __forceinline__ void ldsm2(u32& r0, u32& r1, u32 a) {
    asm volatile("ldmatrix.sync.aligned.m8n8.x2.shared.b16 {%0,%1}, [%2];"
        : "=r"(r0), "=r"(r1) : "r"(a));
}
__device__ __forceinline__ void mma16(float* c, u32 a0, u32 a1, u32 a2, u32 a3,
                                      u32 b0, u32 b1) {
    asm volatile("mma.sync.aligned.m16n8k16.row.col.f32.bf16.bf16.f32 "
        "{%0,%1,%2,%3}, {%4,%5,%6,%7}, {%8,%9}, {%0,%1,%2,%3};"
        : "+f"(c[0]), "+f"(c[1]), "+f"(c[2]), "+f"(c[3])
        : "r"(a0), "r"(a1), "r"(a2), "r"(a3), "r"(b0), "r"(b1));
}
__device__ __forceinline__ void mma8(float* c, float a0, float a1, float a2, float a3,
                                     float b0, float b1) {
    asm volatile("mma.sync.aligned.m16n8k8.row.col.f32.tf32.tf32.f32 "
        "{%0,%1,%2,%3}, {%4,%5,%6,%7}, {%8,%9}, {%0,%1,%2,%3};"
        : "+f"(c[0]), "+f"(c[1]), "+f"(c[2]), "+f"(c[3])
        : "r"(__float_as_uint(a0)), "r"(__float_as_uint(a1)),
          "r"(__float_as_uint(a2)), "r"(__float_as_uint(a3)),
          "r"(__float_as_uint(b0)), "r"(__float_as_uint(b1)));
}

// ---- kernel 1: RMS scales ----
__global__ void rms_kernel(const float* __restrict__ X) {
    int m = blockIdx.x;
    float s = 0.f;
    for (int k = threadIdx.x; k < N_; k += 256) { float v = X[m * N_ + k]; s += v * v; }
    __shared__ float red[256];
    red[threadIdx.x] = s; __syncthreads();
    for (int o = 128; o > 0; o >>= 1) {
        if (threadIdx.x < o) red[threadIdx.x] += red[threadIdx.x + o];
        __syncthreads();
    }
    if (threadIdx.x == 0) g_scale[m] = rsqrtf(red[0] * (1.0f / N_));
}

// ---- kernel 2: QKV GEMM tf32 mma 3-pass, k-split 2, 3-deep pipeline ----
#define QKC 32
#define QXS 36
#define QWS 72
#define QPIPE 3
#define KHALF 1024
__global__ __launch_bounds__(256) void qkv_tc(const float* __restrict__ X,
                                              const float* __restrict__ W) {
    __shared__ float Xs[QPIPE][32 * QXS];
    __shared__ float Ws[QPIPE][QKC * QWS];
    const u32 sbx = cvta_smem(Xs), sbw = cvta_smem(Ws);
    const int t = threadIdx.x, w = t >> 5, lane = t & 31;
    const int gid = lane >> 2, tig = lane & 3;
    const int mt = w & 1, ng = w >> 1;
    const int cb = blockIdx.x * 64;
    const int koff = blockIdx.y * KHALF;

    const float sc0 = g_scale[mt * 16 + gid];
    const float sc1 = g_scale[mt * 16 + gid + 8];

    const int xm = t >> 3, xc = t & 7;
    const int wk = t >> 4, wc = t & 15;

    float acc[2][4];
#pragma unroll
    for (int nb = 0; nb < 2; nb++)
#pragma unroll
        for (int i = 0; i < 4; i++) acc[nb][i] = 0.f;

    const int NST = KHALF / QKC;              // 32 stages

#define QSTAGE(S, BUF) do {                                                   \
        int kb_ = koff + (S) * QKC;                                           \
        cpasync16(sbx + ((BUF) * 32 * QXS + xm * QXS + 4 * xc) * 4,           \
                  &X[xm * N_ + kb_ + 4 * xc]);                                \
        cpasync16(sbw + ((BUF) * QKC * QWS + wk * QWS + 4 * wc) * 4,          \
                  &W[(size_t)(kb_ + wk) * QKV3_ + cb + 4 * wc]);              \
        cpasync16(sbw + ((BUF) * QKC * QWS + (wk + 16) * QWS + 4 * wc) * 4,   \
                  &W[(size_t)(kb_ + wk + 16) * QKV3_ + cb + 4 * wc]);         \
        CP_COMMIT();                                                          \
    } while (0)

    QSTAGE(0, 0);
    QSTAGE(1, 1);

    for (int s = 0; s < NST; s++) {
        __syncthreads();
        if (s + 2 < NST) QSTAGE(s + 2, (s + 2) % QPIPE);
        if (s < NST - 2) { CP_WAIT2(); }
        else if (s == NST - 2) { CP_WAIT1(); }
        else { CP_WAIT0(); }
        __syncthreads();

        const float* xb = Xs[s % QPIPE];
        const float* wb = Ws[s % QPIPE];
#pragma unroll
        for (int k8 = 0; k8 < 4; k8++) {
            int k0 = k8 * 8;
            float xa0 = xb[(mt * 16 + gid) * QXS + k0 + tig] * sc0;
            float xa1 = xb[(mt * 16 + gid + 8) * QXS + k0 + tig] * sc1;
            float xa2 = xb[(mt * 16 + gid) * QXS + k0 + tig + 4] * sc0;
            float xa3 = xb[(mt * 16 + gid + 8) * QXS + k0 + tig + 4] * sc1;
            float ah0 = mh(xa0), al0 = xa0 - ah0;
            float ah1 = mh(xa1), al1 = xa1 - ah1;
            float ah2 = mh(xa2), al2 = xa2 - ah2;
            float ah3 = mh(xa3), al3 = xa3 - ah3;
#pragma unroll
            for (int nb = 0; nb < 2; nb++) {
                int col = ng * 16 + nb * 8 + gid;
                float w0 = wb[(k0 + tig) * QWS + col];
                float w1 = wb[(k0 + tig + 4) * QWS + col];
                float wh0 = mh(w0), wl0 = w0 - wh0;
                float wh1 = mh(w1), wl1 = w1 - wh1;
                mma8(acc[nb], ah0, ah1, ah2, ah3, wh0, wh1);
                mma8(acc[nb], ah0, ah1, ah2, ah3, wl0, wl1);
                mma8(acc[nb], al0, al1, al2, al3, wh0, wh1);
            }
        }
    }

    float* dst = blockIdx.y ? g_qkvB : g_qkv;
#pragma unroll
    for (int nb = 0; nb < 2; nb++) {
        int colg = cb + ng * 16 + nb * 8 + 2 * tig;
        *(float2*)&dst[(mt * 16 + gid) * QKV3_ + colg] =
            make_float2(acc[nb][0], acc[nb][1]);
        *(float2*)&dst[(mt * 16 + gid + 8) * QKV3_ + colg] =
            make_float2(acc[nb][2], acc[nb][3]);
    }
}

// ---- kernel 3: attention (bf16 QK + tf32 PV), 37-chunk grid ----
#define KST_S  132
#define VST_S  136
#define KHI_B  34816
#define KLO_B  51200
#define QHI_B  67584
#define QLO_B  75776
#define ES_F   20992
#define DEN_F  23168
#define SMEMB  92800

__global__ __launch_bounds__(256, 2) void attn_mma(
    const float* __restrict__ cK, const float* __restrict__ cV,
    const int* __restrict__ Pp)
{
    extern __shared__ float smf[];
    char* smb = (char*)smf;
    const u32 sb = cvta_smem(smf);
    const int t = threadIdx.x, w = t >> 5, lane = t & 31;
    const int gid = lane >> 2, tig = lane & 3;
    const int h = blockIdx.y, c = blockIdx.x, P = *Pp;
    const int kg = w >> 1, qh = w & 1;
    const int kb = kg * 16, qb = qh * 16;

    const int nsub = (c < 31) ? 14 : 13;
    const int sub0 = (c < 31) ? 14 * c : 434 + 13 * (c - 31);

    const float* Kh = cK + (size_t)h * L_ * D_;
    const float* Vh = cV + (size_t)h * L_ * D_;

    // ---- stage Q bf16 hi/lo (swizzled), q = sum of k-split halves ----
    {
        int q = t >> 3, c2 = t & 7;
#pragma unroll
        for (int i = 0; i < 2; i++) {
            int ch = 2 * c2 + i;
            int off = q * QKV3_ + h * D_ + 8 * ch;
            float4 xA = *(const float4*)&g_qkv[off];
            float4 xB = *(const float4*)&g_qkvB[off];
            float4 yA = *(const float4*)&g_qkv[off + 4];
            float4 yB = *(const float4*)&g_qkvB[off + 4];
            float4 x = make_float4(xA.x + xB.x, xA.y + xB.y, xA.z + xB.z, xA.w + xB.w);
            float4 y = make_float4(yA.x + yB.x, yA.y + yB.y, yA.z + yB.z, yA.w + yB.w);
            u32 sw = (u32)(q * 256 + ((ch ^ (q & 7)) << 4));
            *(uint4*)(smb + QHI_B + sw) =
                make_uint4(bpack(x.x, x.y), bpack(x.z, x.w), bpack(y.x, y.y), bpack(y.z, y.w));
            float l0 = x.x - bh(x.x), l1 = x.y - bh(x.y), l2 = x.z - bh(x.z), l3 = x.w - bh(x.w);
            float l4 = y.x - bh(y.x), l5 = y.y - bh(y.y), l6 = y.z - bh(y.z), l7 = y.w - bh(y.w);
            *(uint4*)(smb + QLO_B + sw) =
                make_uint4(bpack(l0, l1), bpack(l2, l3), bpack(l4, l5), bpack(l6, l7));
        }
    }
    if (t < 32) smf[DEN_F + t] = 0.f;

    float o[2][2][4];
#pragma unroll
    for (int a = 0; a < 2; a++)
#pragma unroll
        for (int b = 0; b < 2; b++)
#pragma unroll
            for (int k = 0; k < 4; k++) o[a][b][k] = 0.f;

    const int subm = lane >> 3;
    const int rowA = kb + (lane & 7) + ((subm & 1) << 3);
    const int chA  = subm >> 1;
    const int rowB0 = qb + (lane & 7);
    const int chB  = (lane >> 3) & 1;

    // prologue: stage K(0)
    {
        int l0 = sub0 * SK_;
#pragma unroll
        for (int i = 0; i < 8; i++) {
            int idx = t + i * 256, row = idx >> 5, c4 = idx & 31;
            cpasync16(sb + (row * KST_S + 4 * c4) * 4, &Kh[(size_t)(l0 + row) * D_ + 4 * c4]);
        }
        CP_COMMIT();
    }

    for (int s = 0; s < nsub; s++) {
        const int l0 = (sub0 + s) * SK_;
        CP_WAIT0();
        __syncthreads();

        // fresh K rows (sum of halves)
        {
            int lo_ = l0 > P ? l0 : P;
            int hi_ = (l0 + SK_) < (P + M_) ? (l0 + SK_) : (P + M_);
            if (lo_ < hi_) {
                for (int idx = t; idx < (hi_ - lo_) * 32; idx += 256) {
                    int r = idx >> 5, c4 = idx & 31;
                    int gl = lo_ + r;
                    int off = (gl - P) * QKV3_ + N_ + h * D_ + 4 * c4;
                    float4 a = *(const float4*)&g_qkv[off];
                    float4 b = *(const float4*)&g_qkvB[off];
                    *(float4*)&smf[(gl - l0) * KST_S + 4 * c4] =
                        make_float4(a.x + b.x, a.y + b.y, a.z + b.z, a.w + b.w);
                }
                __syncthreads();
            }
        }

        // convert K -> KHI/KLO bf16 (swizzled)
        {
            int row = t >> 2, c4 = t & 3;
            const float* src = smf + row * KST_S;
            char* hid = smb + KHI_B + row * 256;
            char* lod = smb + KLO_B + row * 256;
#pragma unroll
            for (int i = 0; i < 4; i++) {
                int ch = 4 * c4 + i;
                float4 x = *(const float4*)(src + 8 * ch);
                float4 y = *(const float4*)(src + 8 * ch + 4);
                u32 sw = (u32)((ch ^ (row & 7)) << 4);
                *(uint4*)(hid + sw) =
                    make_uint4(bpack(x.x, x.y), bpack(x.z, x.w), bpack(y.x, y.y), bpack(y.z, y.w));
                float l0f = x.x - bh(x.x), l1f = x.y - bh(x.y), l2f = x.z - bh(x.z), l3f = x.w - bh(x.w);
                float l4f = y.x - bh(y.x), l5f = y.y - bh(y.y), l6f = y.z - bh(y.z), l7f = y.w - bh(y.w);
                *(uint4*)(lod + sw) =
                    make_uint4(bpack(l0f, l1f), bpack(l2f, l3f), bpack(l4f, l5f), bpack(l6f, l7f));
            }
        }
        __syncthreads();

        // stage V(s) into staging (stride 136)
#pragma unroll
        for (int i = 0; i < 8; i++) {
            int idx = t + i * 256, row = idx >> 5, c4 = idx & 31;
            cpasync16(sb + (row * VST_S + 4 * c4) * 4, &Vh[(size_t)(l0 + row) * D_ + 4 * c4]);
        }
        CP_COMMIT();

        // QK: bf16 3-pass
        float sc[2][4];
#pragma unroll
        for (int j = 0; j < 2; j++)
#pragma unroll
            for (int k = 0; k < 4; k++) sc[j][k] = 0.f;
#pragma unroll
        for (int ks = 0; ks < 8; ks++) {
            u32 ka0, ka1, ka2, ka3, kl0, kl1, kl2, kl3;
            u32 swA = (u32)(rowA * 256 + (((2 * ks + chA) ^ (rowA & 7)) << 4));
            ldsm4(ka0, ka1, ka2, ka3, sb + KHI_B + swA);
            ldsm4(kl0, kl1, kl2, kl3, sb + KLO_B + swA);
#pragma unroll
            for (int j2 = 0; j2 < 2; j2++) {
                int rowB = rowB0 + j2 * 8;
                u32 swB = (u32)(rowB * 256 + (((2 * ks + chB) ^ (rowB & 7)) << 4));
                u32 qh0, qh1, ql0, ql1;
                ldsm2(qh0, qh1, sb + QHI_B + swB);
                ldsm2(ql0, ql1, sb + QLO_B + swB);
                mma16(sc[j2], ka0, ka1, ka2, ka3, qh0, qh1);
                mma16(sc[j2], kl0, kl1, kl2, kl3, qh0, qh1);
                mma16(sc[j2], ka0, ka1, ka2, ka3, ql0, ql1);
            }
        }

        // exp -> ES, denominators
#pragma unroll
        for (int j2 = 0; j2 < 2; j2++) {
            float e0 = mh(__expf(sc[j2][0]));
            float e1 = mh(__expf(sc[j2][1]));
            float e2 = mh(__expf(sc[j2][2]));
            float e3 = mh(__expf(sc[j2][3]));
            int q0 = qb + j2 * 8 + 2 * tig;
            smf[ES_F + q0 * 68 + kb + gid]           = e0;
            smf[ES_F + (q0 + 1) * 68 + kb + gid]     = e1;
            smf[ES_F + q0 * 68 + kb + gid + 8]       = e2;
            smf[ES_F + (q0 + 1) * 68 + kb + gid + 8] = e3;
            float s0 = e0 + e2, s1 = e1 + e3;
#pragma unroll
            for (int off = 4; off < 32; off <<= 1) {
                s0 += __shfl_xor_sync(0xffffffffu, s0, off);
                s1 += __shfl_xor_sync(0xffffffffu, s1, off);
            }
            if (lane < 4) {
                atomicAdd(&smf[DEN_F + q0], s0);
                atomicAdd(&smf[DEN_F + q0 + 1], s1);
            }
        }

        CP_WAIT0();
        __syncthreads();

        // fresh V rows (sum of halves)
        {
            int lo_ = l0 > P ? l0 : P;
            int hi_ = (l0 + SK_) < (P + M_) ? (l0 + SK_) : (P + M_);
            if (lo_ < hi_) {
                for (int idx = t; idx < (hi_ - lo_) * 32; idx += 256) {
                    int r = idx >> 5, c4 = idx & 31;
                    int gl = lo_ + r;
                    int off = (gl - P) * QKV3_ + 2 * N_ + h * D_ + 4 * c4;
                    float4 a = *(const float4*)&g_qkv[off];
                    float4 b = *(const float4*)&g_qkvB[off];
                    *(float4*)&smf[(gl - l0) * VST_S + 4 * c4] =
                        make_float4(a.x + b.x, a.y + b.y, a.z + b.z, a.w + b.w);
                }
                __syncthreads();
            }
        }

        // PV: E x V (hi/lo 2-pass tf32)
#pragma unroll 2
        for (int ks = 0; ks < 8; ks++) {
            int l = ks * 8;
            float a0[4], a1[4];
            a0[0] = smf[ES_F + gid * 68 + l + tig];
            a0[1] = smf[ES_F + (gid + 8) * 68 + l + tig];
            a0[2] = smf[ES_F + gid * 68 + l + tig + 4];
            a0[3] = smf[ES_F + (gid + 8) * 68 + l + tig + 4];
            a1[0] = smf[ES_F + (16 + gid) * 68 + l + tig];
            a1[1] = smf[ES_F + (24 + gid) * 68 + l + tig];
            a1[2] = smf[ES_F + (16 + gid) * 68 + l + tig + 4];
            a1[3] = smf[ES_F + (24 + gid) * 68 + l + tig + 4];
#pragma unroll
            for (int nb = 0; nb < 2; nb++) {
                int d = w * 16 + nb * 8 + gid;
                float v0 = smf[(l + tig) * VST_S + d];
                float v1 = smf[(l + tig + 4) * VST_S + d];
                float bh0 = mh(v0), bl0 = v0 - bh0;
                float bh1 = mh(v1), bl1 = v1 - bh1;
                mma8(o[0][nb], a0[0], a0[1], a0[2], a0[3], bh0, bh1);
                mma8(o[0][nb], a0[0], a0[1], a0[2], a0[3], bl0, bl1);
                mma8(o[1][nb], a1[0], a1[1], a1[2], a1[3], bh0, bh1);
                mma8(o[1][nb], a1[0], a1[1], a1[2], a1[3], bl0, bl1);
            }
        }
        __syncthreads();

        if (s + 1 < nsub) {                   // stage K(s+1)
            int ln = l0 + SK_;
#pragma unroll
            for (int i = 0; i < 8; i++) {
                int idx = t + i * 256, row = idx >> 5, c4 = idx & 31;
                cpasync16(sb + (row * KST_S + 4 * c4) * 4, &Kh[(size_t)(ln + row) * D_ + 4 * c4]);
            }
            CP_COMMIT();
        }
    }

    // epilogue
    const size_t base = (size_t)(h * NCC_ + c) * M_ * D_;
#pragma unroll
    for (int mt = 0; mt < 2; mt++)
#pragma unroll
        for (int nb = 0; nb < 2; nb++) {
            int q0 = mt * 16 + gid, d0 = w * 16 + nb * 8 + 2 * tig;
            *(float2*)&g_num[base + (size_t)q0 * D_ + d0] =
                make_float2(o[mt][nb][0], o[mt][nb][1]);
            *(float2*)&g_num[base + (size_t)(q0 + 8) * D_ + d0] =
                make_float2(o[mt][nb][2], o[mt][nb][3]);
        }
    if (t < 32) g_den[(h * NCC_ + c) * M_ + t] = smf[DEN_F + t];
}

// ---- kernel 4: reduce (37 chunks, 4-way parallel) ----
__global__ __launch_bounds__(512) void reduce_out(float* __restrict__ out) {
    __shared__ float part[512];
    int hm = blockIdx.x, h = hm >> 5, m = hm & 31;
    int t = threadIdx.x, d = t & 127, cg = t >> 7;
    float nsum = 0.f;
    for (int i = 0; i < 10; i++) {
        int c = cg * 10 + i;
        if (c < NCC_)
            nsum += g_num[((size_t)(h * NCC_ + c) * M_ + m) * D_ + d];
    }
    part[t] = nsum;
    __syncthreads();
    if (t < 128) {
        float tot = part[t] + part[t + 128] + part[t + 256] + part[t + 384];
        float dsum = 0.f;
        for (int c = 0; c < NCC_; c++) dsum += g_den[(h * NCC_ + c) * M_ + m];
        out[m * N_ + h * D_ + d] = tot / dsum;
    }
}

extern "C" void kernel_launch(void* const* d_in, const int* in_sizes, int n_in,
                              void* d_out, int out_size) {
    const float* X  = (const float*)d_in[0];
    const float* W  = (const float*)d_in[1];
    const float* cK = (const float*)d_in[2];
    const float* cV = (const float*)d_in[3];
    const int*   P  = (const int*)d_in[4];
    float* out = (float*)d_out;

    cudaFuncSetAttribute(attn_mma, cudaFuncAttributeMaxDynamicSharedMemorySize, SMEMB);

    rms_kernel<<<M_, 256>>>(X);
    qkv_tc<<<dim3(QKV3_ / 64, 2), 256>>>(X, W);
    attn_mma<<<dim3(NCC_, H_), 256, SMEMB>>>(cK, cV, P);
    reduce_out<<<H_ * M_, 512>>>(out);
}

// round 16
// speedup vs baseline: 1.1877x; 1.0337x over previous
#include <cuda_runtime.h>
#include <cstdint>

#define M_     32
#define N_     2048
#define D_     128
#define L_     32768
#define H_     16
#define QKV3_  6144
#define SK_    64          // keys per subtile
#define NCC_   37          // chunks (31x14 + 6x13 subtiles = 512)

typedef unsigned long long u64;
typedef unsigned int u32;

__device__ float g_scale[M_];
__device__ float g_qkv[M_ * QKV3_];
__device__ float g_qkvB[M_ * QKV3_];
__device__ float g_qkvC[M_ * QKV3_];
__device__ float g_num[H_ * NCC_ * M_ * D_];
__device__ float g_den[H_ * NCC_ * M_];

// ---- helpers ----
__device__ __forceinline__ float mh(float x) {
    return __uint_as_float(__float_as_uint(x) & 0xFFFFE000u);
}
__device__ __forceinline__ float bh(float x) {
    return __uint_as_float(__float_as_uint(x) & 0xFFFF0000u);
}
__device__ __forceinline__ u32 bpack(float a, float b) {
    u32 r;
    asm("prmt.b32 %0, %1, %2, 0x7632;" : "=r"(r)
        : "r"(__float_as_uint(a)), "r"(__float_as_uint(b)));
    return r;
}
__device__ __forceinline__ u32 cvta_smem(const void* p) {
    u32 a; asm("{ .reg .u64 t; cvta.to.shared.u64 t, %1; cvt.u32.u64 %0, t; }" : "=r"(a) : "l"(p)); return a;
}
__device__ __forceinline__ void cpasync16(u32 s, const void* g) {
    asm volatile("cp.async.cg.shared.global [%0], [%1], 16;" :: "r"(s), "l"(g));
}
#define CP_COMMIT() asm volatile("cp.async.commit_group;" ::: "memory")
#define CP_WAIT0()  asm volatile("cp.async.wait_group 0;" ::: "memory")
#define CP_WAIT1()  asm volatile("cp.async.wait_group 1;" ::: "memory")
#define CP_WAIT2()  asm volatile("cp.async.wait_group 2;" ::: "memory")

__device__ __forceinline__ void ldsm4(u32& r0, u32& r1, u32& r2, u32& r3, u32 a) {
    asm volatile("ldmatrix.sync.aligned.m8n8.x4.shared.b16 {%0,%1,%2,%3}, [%4];"
        : "=r"(r0), "=r"(r1), "=r"(r2), "=r"(r3) : "r"(a));
}
__device__ __forceinline__ void ldsm2(u32& r0, u32& r1, u32 a) {
    asm volatile("ldmatrix.sync.aligned.m8n8.x2.shared.b16 {%0,%1}, [%2];"
        : "=r"(r0), "=r"(r1) : "r"(a));
}
__device__ __forceinline__ void mma16(float* c, u32 a0, u32 a1, u32 a2, u32 a3,
                                      u32 b0, u32 b1) {
    asm volatile("mma.sync.aligned.m16n8k16.row.col.f32.bf16.bf16.f32 "
        "{%0,%1,%2,%3}, {%4,%5,%6,%7}, {%8,%9}, {%0,%1,%2,%3};"
        : "+f"(c[0]), "+f"(c[1]), "+f"(c[2]), "+f"(c[3])
        : "r"(a0), "r"(a1), "r"(a2), "r"(a3), "r"(b0), "r"(b1));
}
__device__ __forceinline__ void mma8(float* c, float a0, float a1, float a2, float a3,
                                     float b0, float b1) {
    asm volatile("mma.sync.aligned.m16n8k8.row.col.f32.tf32.tf32.f32 "
        "{%0,%1,%2,%3}, {%4,%5,%6,%7}, {%8,%9}, {%0,%1,%2,%3};"
        : "+f"(c[0]), "+f"(c[1]), "+f"(c[2]), "+f"(c[3])
        : "r"(__float_as_uint(a0)), "r"(__float_as_uint(a1)),
          "r"(__float_as_uint(a2)), "r"(__float_as_uint(a3)),
          "r"(__float_as_uint(b0)), "r"(__float_as_uint(b1)));
}

// ---- kernel 1: RMS scales ----
__global__ void rms_kernel(const float* __restrict__ X) {
    int m = blockIdx.x;
    float s = 0.f;
    for (int k = threadIdx.x; k < N_; k += 256) { float v = X[m * N_ + k]; s += v * v; }
    __shared__ float red[256];
    red[threadIdx.x] = s; __syncthreads();
    for (int o = 128; o > 0; o >>= 1) {
        if (threadIdx.x < o) red[threadIdx.x] += red[threadIdx.x + o];
        __syncthreads();
    }
    if (threadIdx.x == 0) g_scale[m] = rsqrtf(red[0] * (1.0f / N_));
}

// ---- kernel 2: QKV GEMM tf32 mma 3-pass, k-split 3 (288 CTAs) ----
#define QKC 32
#define QXS 36
#define QWS 72
#define QPIPE 3
#define KSLAB 672           // 21*32 ; last slab 704 = 22*32
__global__ __launch_bounds__(256) void qkv_tc(const float* __restrict__ X,
                                              const float* __restrict__ W) {
    __shared__ float Xs[QPIPE][32 * QXS];
    __shared__ float Ws[QPIPE][QKC * QWS];
    const u32 sbx = cvta_smem(Xs), sbw = cvta_smem(Ws);
    const int t = threadIdx.x, w = t >> 5, lane = t & 31;
    const int gid = lane >> 2, tig = lane & 3;
    const int mt = w & 1, ng = w >> 1;
    const int cb = blockIdx.x * 64;
    const int koff = blockIdx.y * KSLAB;
    const int NST = (blockIdx.y == 2) ? 22 : 21;

    const float sc0 = g_scale[mt * 16 + gid];
    const float sc1 = g_scale[mt * 16 + gid + 8];

    const int xm = t >> 3, xc = t & 7;
    const int wk = t >> 4, wc = t & 15;

    float acc[2][4];
#pragma unroll
    for (int nb = 0; nb < 2; nb++)
#pragma unroll
        for (int i = 0; i < 4; i++) acc[nb][i] = 0.f;

#define QSTAGE(S, BUF) do {                                                   \
        int kb_ = koff + (S) * QKC;                                           \
        cpasync16(sbx + ((BUF) * 32 * QXS + xm * QXS + 4 * xc) * 4,           \
                  &X[xm * N_ + kb_ + 4 * xc]);                                \
        cpasync16(sbw + ((BUF) * QKC * QWS + wk * QWS + 4 * wc) * 4,          \
                  &W[(size_t)(kb_ + wk) * QKV3_ + cb + 4 * wc]);              \
        cpasync16(sbw + ((BUF) * QKC * QWS + (wk + 16) * QWS + 4 * wc) * 4,   \
                  &W[(size_t)(kb_ + wk + 16) * QKV3_ + cb + 4 * wc]);         \
        CP_COMMIT();                                                          \
    } while (0)

    QSTAGE(0, 0);
    QSTAGE(1, 1);

    for (int s = 0; s < NST; s++) {
        __syncthreads();
        if (s + 2 < NST) QSTAGE(s + 2, (s + 2) % QPIPE);
        if (s < NST - 2) { CP_WAIT2(); }
        else if (s == NST - 2) { CP_WAIT1(); }
        else { CP_WAIT0(); }
        __syncthreads();

        const float* xb = Xs[s % QPIPE];
        const float* wb = Ws[s % QPIPE];
#pragma unroll
        for (int k8 = 0; k8 < 4; k8++) {
            int k0 = k8 * 8;
            float xa0 = xb[(mt * 16 + gid) * QXS + k0 + tig] * sc0;
            float xa1 = xb[(mt * 16 + gid + 8) * QXS + k0 + tig] * sc1;
            float xa2 = xb[(mt * 16 + gid) * QXS + k0 + tig + 4] * sc0;
            float xa3 = xb[(mt * 16 + gid + 8) * QXS + k0 + tig + 4] * sc1;
            float ah0 = mh(xa0), al0 = xa0 - ah0;
            float ah1 = mh(xa1), al1 = xa1 - ah1;
            float ah2 = mh(xa2), al2 = xa2 - ah2;
            float ah3 = mh(xa3), al3 = xa3 - ah3;
#pragma unroll
            for (int nb = 0; nb < 2; nb++) {
                int col = ng * 16 + nb * 8 + gid;
                float w0 = wb[(k0 + tig) * QWS + col];
                float w1 = wb[(k0 + tig + 4) * QWS + col];
                float wh0 = mh(w0), wl0 = w0 - wh0;
                float wh1 = mh(w1), wl1 = w1 - wh1;
                mma8(acc[nb], ah0, ah1, ah2, ah3, wh0, wh1);
                mma8(acc[nb], ah0, ah1, ah2, ah3, wl0, wl1);
                mma8(acc[nb], al0, al1, al2, al3, wh0, wh1);
            }
        }
    }

    float* dst = (blockIdx.y == 0) ? g_qkv : (blockIdx.y == 1 ? g_qkvB : g_qkvC);
#pragma unroll
    for (int nb = 0; nb < 2; nb++) {
        int colg = cb + ng * 16 + nb * 8 + 2 * tig;
        *(float2*)&dst[(mt * 16 + gid) * QKV3_ + colg] =
            make_float2(acc[nb][0], acc[nb][1]);
        *(float2*)&dst[(mt * 16 + gid + 8) * QKV3_ + colg] =
            make_float2(acc[nb][2], acc[nb][3]);
    }
}

// ---- kernel 3: attention (bf16 QK + tf32 PV), 37-chunk grid ----
#define KST_S  132
#define VST_S  136
#define KHI_B  34816
#define KLO_B  51200
#define QHI_B  67584
#define QLO_B  75776
#define ES_F   20992
#define DEN_F  23168
#define SMEMB  92800

__global__ __launch_bounds__(256, 2) void attn_mma(
    const float* __restrict__ cK, const float* __restrict__ cV,
    const int* __restrict__ Pp)
{
    extern __shared__ float smf[];
    char* smb = (char*)smf;
    const u32 sb = cvta_smem(smf);
    const int t = threadIdx.x, w = t >> 5, lane = t & 31;
    const int gid = lane >> 2, tig = lane & 3;
    const int h = blockIdx.y, c = blockIdx.x, P = *Pp;
    const int kg = w >> 1, qh = w & 1;
    const int kb = kg * 16, qb = qh * 16;

    const int nsub = (c < 31) ? 14 : 13;
    const int sub0 = (c < 31) ? 14 * c : 434 + 13 * (c - 31);

    const float* Kh = cK + (size_t)h * L_ * D_;
    const float* Vh = cV + (size_t)h * L_ * D_;

    // ---- stage Q bf16 hi/lo (swizzled), q = sum of 3 k-split buffers ----
    {
        int q = t >> 3, c2 = t & 7;
#pragma unroll
        for (int i = 0; i < 2; i++) {
            int ch = 2 * c2 + i;
            int off = q * QKV3_ + h * D_ + 8 * ch;
            float4 xA = *(const float4*)&g_qkv[off];
            float4 xB = *(const float4*)&g_qkvB[off];
            float4 xC = *(const float4*)&g_qkvC[off];
            float4 yA = *(const float4*)&g_qkv[off + 4];
            float4 yB = *(const float4*)&g_qkvB[off + 4];
            float4 yC = *(const float4*)&g_qkvC[off + 4];
            float4 x = make_float4(xA.x + xB.x + xC.x, xA.y + xB.y + xC.y,
                                   xA.z + xB.z + xC.z, xA.w + xB.w + xC.w);
            float4 y = make_float4(yA.x + yB.x + yC.x, yA.y + yB.y + yC.y,
                                   yA.z + yB.z + yC.z, yA.w + yB.w + yC.w);
            u32 sw = (u32)(q * 256 + ((ch ^ (q & 7)) << 4));
            *(uint4*)(smb + QHI_B + sw) =
                make_uint4(bpack(x.x, x.y), bpack(x.z, x.w), bpack(y.x, y.y), bpack(y.z, y.w));
            float l0 = x.x - bh(x.x), l1 = x.y - bh(x.y), l2 = x.z - bh(x.z), l3 = x.w - bh(x.w);
            float l4 = y.x - bh(y.x), l5 = y.y - bh(y.y), l6 = y.z - bh(y.z), l7 = y.w - bh(y.w);
            *(uint4*)(smb + QLO_B + sw) =
                make_uint4(bpack(l0, l1), bpack(l2, l3), bpack(l4, l5), bpack(l6, l7));
        }
    }
    if (t < 32) smf[DEN_F + t] = 0.f;

    float o[2][2][4];
#pragma unroll
    for (int a = 0; a < 2; a++)
#pragma unroll
        for (int b = 0; b < 2; b++)
#pragma unroll
            for (int k = 0; k < 4; k++) o[a][b][k] = 0.f;

    const int subm = lane >> 3;
    const int rowA = kb + (lane & 7) + ((subm & 1) << 3);
    const int chA  = subm >> 1;
    const int rowB0 = qb + (lane & 7);
    const int chB  = (lane >> 3) & 1;

    // prologue: stage K(0)
    {
        int l0 = sub0 * SK_;
#pragma unroll
        for (int i = 0; i < 8; i++) {
            int idx = t + i * 256, row = idx >> 5, c4 = idx & 31;
            cpasync16(sb + (row * KST_S + 4 * c4) * 4, &Kh[(size_t)(l0 + row) * D_ + 4 * c4]);
        }
        CP_COMMIT();
    }

    for (int s = 0; s < nsub; s++) {
        const int l0 = (sub0 + s) * SK_;
        CP_WAIT0();
        __syncthreads();

        // fresh K rows (sum of 3 buffers)
        {
            int lo_ = l0 > P ? l0 : P;
            int hi_ = (l0 + SK_) < (P + M_) ? (l0 + SK_) : (P + M_);
            if (lo_ < hi_) {
                for (int idx = t; idx < (hi_ - lo_) * 32; idx += 256) {
                    int r = idx >> 5, c4 = idx & 31;
                    int gl = lo_ + r;
                    int off = (gl - P) * QKV3_ + N_ + h * D_ + 4 * c4;
                    float4 a = *(const float4*)&g_qkv[off];
                    float4 b = *(const float4*)&g_qkvB[off];
                    float4 cc = *(const float4*)&g_qkvC[off];
                    *(float4*)&smf[(gl - l0) * KST_S + 4 * c4] =
                        make_float4(a.x + b.x + cc.x, a.y + b.y + cc.y,
                                    a.z + b.z + cc.z, a.w + b.w + cc.w);
                }
                __syncthreads();
            }
        }

        // convert K -> KHI/KLO bf16 (swizzled)
        {
            int row = t >> 2, c4 = t & 3;
            const float* src = smf + row * KST_S;
            char* hid = smb + KHI_B + row * 256;
            char* lod = smb + KLO_B + row * 256;
#pragma unroll
            for (int i = 0; i < 4; i++) {
                int ch = 4 * c4 + i;
                float4 x = *(const float4*)(src + 8 * ch);
                float4 y = *(const float4*)(src + 8 * ch + 4);
                u32 sw = (u32)((ch ^ (row & 7)) << 4);
                *(uint4*)(hid + sw) =
                    make_uint4(bpack(x.x, x.y), bpack(x.z, x.w), bpack(y.x, y.y), bpack(y.z, y.w));
                float l0f = x.x - bh(x.x), l1f = x.y - bh(x.y), l2f = x.z - bh(x.z), l3f = x.w - bh(x.w);
                float l4f = y.x - bh(y.x), l5f = y.y - bh(y.y), l6f = y.z - bh(y.z), l7f = y.w - bh(y.w);
                *(uint4*)(lod + sw) =
                    make_uint4(bpack(l0f, l1f), bpack(l2f, l3f), bpack(l4f, l5f), bpack(l6f, l7f));
            }
        }
        __syncthreads();

        // stage V(s) into staging (stride 136)
#pragma unroll
        for (int i = 0; i < 8; i++) {
            int idx = t + i * 256, row = idx >> 5, c4 = idx & 31;
            cpasync16(sb + (row * VST_S + 4 * c4) * 4, &Vh[(size_t)(l0 + row) * D_ + 4 * c4]);
        }
        CP_COMMIT();

        // QK: bf16 3-pass
        float sc[2][4];
#pragma unroll
        for (int j = 0; j < 2; j++)
#pragma unroll
            for (int k = 0; k < 4; k++) sc[j][k] = 0.f;
#pragma unroll
        for (int ks = 0; ks < 8; ks++) {
            u32 ka0, ka1, ka2, ka3, kl0, kl1, kl2, kl3;
            u32 swA = (u32)(rowA * 256 + (((2 * ks + chA) ^ (rowA & 7)) << 4));
            ldsm4(ka0, ka1, ka2, ka3, sb + KHI_B + swA);
            ldsm4(kl0, kl1, kl2, kl3, sb + KLO_B + swA);
#pragma unroll
            for (int j2 = 0; j2 < 2; j2++) {
                int rowB = rowB0 + j2 * 8;
                u32 swB = (u32)(rowB * 256 + (((2 * ks + chB) ^ (rowB & 7)) << 4));
                u32 qh0, qh1, ql0, ql1;
                ldsm2(qh0, qh1, sb + QHI_B + swB);
                ldsm2(ql0, ql1, sb + QLO_B + swB);
                mma16(sc[j2], ka0, ka1, ka2, ka3, qh0, qh1);
                mma16(sc[j2], kl0, kl1, kl2, kl3, qh0, qh1);
                mma16(sc[j2], ka0, ka1, ka2, ka3, ql0, ql1);
            }
        }

        // exp -> ES, denominators
#pragma unroll
        for (int j2 = 0; j2 < 2; j2++) {
            float e0 = mh(__expf(sc[j2][0]));
            float e1 = mh(__expf(sc[j2][1]));
            float e2 = mh(__expf(sc[j2][2]));
            float e3 = mh(__expf(sc[j2][3]));
            int q0 = qb + j2 * 8 + 2 * tig;
            smf[ES_F + q0 * 68 + kb + gid]           = e0;
            smf[ES_F + (q0 + 1) * 68 + kb + gid]     = e1;
            smf[ES_F + q0 * 68 + kb + gid + 8]       = e2;
            smf[ES_F + (q0 + 1) * 68 + kb + gid + 8] = e3;
            float s0 = e0 + e2, s1 = e1 + e3;
#pragma unroll
            for (int off = 4; off < 32; off <<= 1) {
                s0 += __shfl_xor_sync(0xffffffffu, s0, off);
                s1 += __shfl_xor_sync(0xffffffffu, s1, off);
            }
            if (lane < 4) {
                atomicAdd(&smf[DEN_F + q0], s0);
                atomicAdd(&smf[DEN_F + q0 + 1], s1);
            }
        }

        CP_WAIT0();
        __syncthreads();

        // fresh V rows (sum of 3 buffers)
        {
            int lo_ = l0 > P ? l0 : P;
            int hi_ = (l0 + SK_) < (P + M_) ? (l0 + SK_) : (P + M_);
            if (lo_ < hi_) {
                for (int idx = t; idx < (hi_ - lo_) * 32; idx += 256) {
                    int r = idx >> 5, c4 = idx & 31;
                    int gl = lo_ + r;
                    int off = (gl - P) * QKV3_ + 2 * N_ + h * D_ + 4 * c4;
                    float4 a = *(const float4*)&g_qkv[off];
                    float4 b = *(const float4*)&g_qkvB[off];
                    float4 cc = *(const float4*)&g_qkvC[off];
                    *(float4*)&smf[(gl - l0) * VST_S + 4 * c4] =
                        make_float4(a.x + b.x + cc.x, a.y + b.y + cc.y,
                                    a.z + b.z + cc.z, a.w + b.w + cc.w);
                }
                __syncthreads();
            }
        }

        // PV: E x V (hi/lo 2-pass tf32)
#pragma unroll 2
        for (int ks = 0; ks < 8; ks++) {
            int l = ks * 8;
            float a0[4], a1[4];
            a0[0] = smf[ES_F + gid * 68 + l + tig];
            a0[1] = smf[ES_F + (gid + 8) * 68 + l + tig];
            a0[2] = smf[ES_F + gid * 68 + l + tig + 4];
            a0[3] = smf[ES_F + (gid + 8) * 68 + l + tig + 4];
            a1[0] = smf[ES_F + (16 + gid) * 68 + l + tig];
            a1[1] = smf[ES_F + (24 + gid) * 68 + l + tig];
            a1[2] = smf[ES_F + (16 + gid) * 68 + l + tig + 4];
            a1[3] = smf[ES_F + (24 + gid) * 68 + l + tig + 4];
#pragma unroll
            for (int nb = 0; nb < 2; nb++) {
                int d = w * 16 + nb * 8 + gid;
                float v0 = smf[(l + tig) * VST_S + d];
                float v1 = smf[(l + tig + 4) * VST_S + d];
                float bh0 = mh(v0), bl0 = v0 - bh0;
                float bh1 = mh(v1), bl1 = v1 - bh1;
                mma8(o[0][nb], a0[0], a0[1], a0[2], a0[3], bh0, bh1);
                mma8(o[0][nb], a0[0], a0[1], a0[2], a0[3], bl0, bl1);
                mma8(o[1][nb], a1[0], a1[1], a1[2], a1[3], bh0, bh1);
                mma8(o[1][nb], a1[0], a1[1], a1[2], a1[3], bl0, bl1);
            }
        }
        __syncthreads();

        if (s + 1 < nsub) {                   // stage K(s+1)
            int ln = l0 + SK_;
#pragma unroll
            for (int i = 0; i < 8; i++) {
                int idx = t + i * 256, row = idx >> 5, c4 = idx & 31;
                cpasync16(sb + (row * KST_S + 4 * c4) * 4, &Kh[(size_t)(ln + row) * D_ + 4 * c4]);
            }
            CP_COMMIT();
        }
    }

    // epilogue
    const size_t base = (size_t)(h * NCC_ + c) * M_ * D_;
#pragma unroll
    for (int mt = 0; mt < 2; mt++)
#pragma unroll
        for (int nb = 0; nb < 2; nb++) {
            int q0 = mt * 16 + gid, d0 = w * 16 + nb * 8 + 2 * tig;
            *(float2*)&g_num[base + (size_t)q0 * D_ + d0] =
                make_float2(o[mt][nb][0], o[mt][nb][1]);
            *(float2*)&g_num[base + (size_t)(q0 + 8) * D_ + d0] =
                make_float2(o[mt][nb][2], o[mt][nb][3]);
        }
    if (t < 32) g_den[(h * NCC_ + c) * M_ + t] = smf[DEN_F + t];
}

// ---- kernel 4: reduce (float4, 16-way chunk parallel) ----
__global__ __launch_bounds__(512) void reduce_out(float* __restrict__ out) {
    __shared__ float part[16 * 128];
    __shared__ float denp[16];
    int hm = blockIdx.x, h = hm >> 5, m = hm & 31;
    int t = threadIdx.x, d4 = t & 31, cg = t >> 5;   // 16 chunk-groups x 32 d4
    float4 ns = make_float4(0.f, 0.f, 0.f, 0.f);
    float dn = 0.f;
#pragma unroll
    for (int i = 0; i < 3; i++) {
        int c = cg + 16 * i;
        if (c < NCC_) {
            float4 v = *(const float4*)&g_num[((size_t)(h * NCC_ + c) * M_ + m) * D_ + 4 * d4];
            ns.x += v.x; ns.y += v.y; ns.z += v.z; ns.w += v.w;
            if (d4 == 0) dn += g_den[(h * NCC_ + c) * M_ + m];
        }
    }
    *(float4*)&part[cg * 128 + 4 * d4] = ns;
    if (d4 == 0) denp[cg] = dn;
    __syncthreads();
    if (t < 128) {
        float tot = 0.f;
#pragma unroll
        for (int g = 0; g < 16; g++) tot += part[g * 128 + t];
        float dsum = 0.f;
#pragma unroll
        for (int g = 0; g < 16; g++) dsum += denp[g];
        out[m * N_ + h * D_ + t] = tot / dsum;
    }
}

extern "C" void kernel_launch(void* const* d_in, const int* in_sizes, int n_in,
                              void* d_out, int out_size) {
    const float* X  = (const float*)d_in[0];
    const float* W  = (const float*)d_in[1];
    const float* cK = (const float*)d_in[2];
    const float* cV = (const float*)d_in[3];
    const int*   P  = (const int*)d_in[4];
    float* out = (float*)d_out;

    cudaFuncSetAttribute(attn_mma, cudaFuncAttributeMaxDynamicSharedMemorySize, SMEMB);

    rms_kernel<<<M_, 256>>>(X);
    qkv_tc<<<dim3(QKV3_ / 64, 3), 256>>>(X, W);
    attn_mma<<<dim3(NCC_, H_), 256, SMEMB>>>(cK, cV, P);
    reduce_out<<<H_ * M_, 512>>>(out);
}